// round 11
// baseline (speedup 1.0000x reference)
#include <cuda_runtime.h>
#include <cuda_fp16.h>
#include <cstdint>
#include <math.h>

#define N_NODES 100000
#define N_FEAT  100
#define HID     32
#define N_EDGES 1600000
#define ELL_CAP 128         // max in-degree slot (Poisson(16): P(>128) ~ 0)
#define K1_NB   128         // nodes per block in k1 (= threads)

// Scratch (static device globals — no allocations allowed)
__device__ float g_xnf[N_NODES * HID];                   // fp32 normalized feats
__device__ __align__(16) unsigned g_xnh[N_NODES * 16];   // half2-packed rows (64B)
__device__ float g_nrm[N_NODES];                         // row norms
__device__ int   g_cnt[N_NODES];                         // in-degree counters
__device__ int   g_col[N_NODES * ELL_CAP];               // ELL source lists

// ---------------- packed f32x2 helpers (sm_100+) ----------------
__device__ __forceinline__ unsigned long long ffma2(
    unsigned long long a, unsigned long long b, unsigned long long c) {
    unsigned long long d;
    asm("fma.rn.f32x2 %0, %1, %2, %3;" : "=l"(d) : "l"(a), "l"(b), "l"(c));
    return d;
}
__device__ __forceinline__ float unpack_add(unsigned long long v) {
    float lo, hi;
    asm("mov.b64 {%0, %1}, %2;" : "=f"(lo), "=f"(hi) : "l"(v));
    return lo + hi;
}

// ---------------------------------------------------------------------------
// K1: x = relu(X @ W1^T + b1); xn = x/||x||. Thread-per-node.
// X staged row-major in smem (coalesced in, conflict-free stride-25 LDS.128
// out). Weights read as WARP-UNIFORM LDG.128 -> single L1 wavefront each,
// broadcast to all lanes; W1 (12.8KB) stays L1-resident. 32 f32x2 acc chains.
// ---------------------------------------------------------------------------
__global__ void __launch_bounds__(K1_NB) k1_lin(
    const float* __restrict__ X,
    const float* __restrict__ W1,
    const float* __restrict__ b1)
{
    extern __shared__ float4 sX4[];            // [K1_NB * 25]
    const int tid   = threadIdx.x;
    const int node0 = blockIdx.x * K1_NB;
    const int nN    = min(K1_NB, N_NODES - node0);

    const float4* X4 = (const float4*)X;
    for (int i = tid; i < nN * 25; i += K1_NB)
        sX4[i] = X4[(size_t)node0 * 25 + i];   // fully coalesced
    __syncthreads();

    if (tid >= nN) return;
    const int node = node0 + tid;

    unsigned long long acc[HID];
    #pragma unroll
    for (int h = 0; h < HID; h++) acc[h] = 0ull;

    const ulonglong2* sX2 = (const ulonglong2*)sX4;
    const ulonglong2* W2v = (const ulonglong2*)W1;   // [h*100+c*4] floats, 16B ok
    #pragma unroll 5
    for (int c = 0; c < 25; c++) {
        const ulonglong2 x = sX2[tid * 25 + c];      // LDS.128, conflict-free
        #pragma unroll
        for (int h = 0; h < HID; h++) {
            // warp-uniform address -> broadcast LDG.128, 1 wavefront, L1-hot
            const ulonglong2 w = __ldg(&W2v[(h * N_FEAT + c * 4) >> 2]);
            acc[h] = ffma2(x.x, w.x, acc[h]);
            acc[h] = ffma2(x.y, w.y, acc[h]);
        }
    }

    float v[HID];
    float ss = 0.f;
    #pragma unroll
    for (int h = 0; h < HID; h++) {
        float t = fmaxf(unpack_add(acc[h]) + __ldg(&b1[h]), 0.f);
        v[h] = t;
        ss += t * t;
    }
    const float nrm = fmaxf(sqrtf(ss), 1e-12f);
    const float inv = 1.0f / nrm;

    float4* xf = (float4*)&g_xnf[node * HID];
    uint4*  xh = (uint4*)&g_xnh[node * 16];
    #pragma unroll
    for (int j = 0; j < 8; j++)
        xf[j] = make_float4(v[j*4+0]*inv, v[j*4+1]*inv,
                            v[j*4+2]*inv, v[j*4+3]*inv);
    #pragma unroll
    for (int q = 0; q < 4; q++) {
        __half2 h0 = __floats2half2_rn(v[q*8+0]*inv, v[q*8+1]*inv);
        __half2 h1 = __floats2half2_rn(v[q*8+2]*inv, v[q*8+3]*inv);
        __half2 h2 = __floats2half2_rn(v[q*8+4]*inv, v[q*8+5]*inv);
        __half2 h3 = __floats2half2_rn(v[q*8+6]*inv, v[q*8+7]*inv);
        xh[q] = make_uint4(*(unsigned*)&h0, *(unsigned*)&h1,
                           *(unsigned*)&h2, *(unsigned*)&h3);
    }
    g_nrm[node] = nrm;
    g_cnt[node] = 0;
}

// ---------------------------------------------------------------------------
// ELL build: 4 edges per thread, int4 reads, 4 independent atomic chains.
// ---------------------------------------------------------------------------
__global__ void k_ell(const int* __restrict__ esrc,
                      const int* __restrict__ etgt) {
    int e0 = (blockIdx.x * blockDim.x + threadIdx.x) * 4;
    if (e0 >= N_EDGES) return;
    int4 s = *(const int4*)&esrc[e0];
    int4 t = *(const int4*)&etgt[e0];
    int p0 = atomicAdd(&g_cnt[t.x], 1);
    int p1 = atomicAdd(&g_cnt[t.y], 1);
    int p2 = atomicAdd(&g_cnt[t.z], 1);
    int p3 = atomicAdd(&g_cnt[t.w], 1);
    if (p0 < ELL_CAP) g_col[t.x * ELL_CAP + p0] = s.x;
    if (p1 < ELL_CAP) g_col[t.y * ELL_CAP + p1] = s.y;
    if (p2 < ELL_CAP) g_col[t.z * ELL_CAP + p2] = s.z;
    if (p3 < ELL_CAP) g_col[t.w * ELL_CAP + p3] = s.w;
}

// ---------------------------------------------------------------------------
// K_AGG: 8-lane group owns one node (4 nodes/warp); fp16 gathers; 4-way MLP.
// ---------------------------------------------------------------------------
__device__ __forceinline__ void edge4(
    int cb, int jj, int deg, int cidx, unsigned gmask, int n, int sub,
    const float4 xt, float beta, float4& acc, float& den)
{
    const bool v0 = (cb + jj     < deg);
    const bool v1 = (cb + jj + 1 < deg);
    const bool v2 = (cb + jj + 2 < deg);
    const bool v3 = (cb + jj + 3 < deg);
    int s0 = __shfl_sync(gmask, cidx, jj,     8);
    int s1 = __shfl_sync(gmask, cidx, jj + 1, 8);
    int s2 = __shfl_sync(gmask, cidx, jj + 2, 8);
    int s3 = __shfl_sync(gmask, cidx, jj + 3, 8);
    s0 = v0 ? s0 : n;  s1 = v1 ? s1 : n;
    s2 = v2 ? s2 : n;  s3 = v3 ? s3 : n;

    const uint2 u0 = *(const uint2*)&g_xnh[s0 * 16 + sub * 2];
    const uint2 u1 = *(const uint2*)&g_xnh[s1 * 16 + sub * 2];
    const uint2 u2 = *(const uint2*)&g_xnh[s2 * 16 + sub * 2];
    const uint2 u3 = *(const uint2*)&g_xnh[s3 * 16 + sub * 2];
    const float r0 = g_nrm[s0], r1 = g_nrm[s1];
    const float r2 = g_nrm[s2], r3 = g_nrm[s3];

    float2 a0 = __half22float2(*(const __half2*)&u0.x);
    float2 b0 = __half22float2(*(const __half2*)&u0.y);
    float2 a1 = __half22float2(*(const __half2*)&u1.x);
    float2 b1 = __half22float2(*(const __half2*)&u1.y);
    float2 a2 = __half22float2(*(const __half2*)&u2.x);
    float2 b2 = __half22float2(*(const __half2*)&u2.y);
    float2 a3 = __half22float2(*(const __half2*)&u3.x);
    float2 b3 = __half22float2(*(const __half2*)&u3.y);

    float d0 = a0.x*xt.x + a0.y*xt.y + b0.x*xt.z + b0.y*xt.w;
    float d1 = a1.x*xt.x + a1.y*xt.y + b1.x*xt.z + b1.y*xt.w;
    float d2 = a2.x*xt.x + a2.y*xt.y + b2.x*xt.z + b2.y*xt.w;
    float d3 = a3.x*xt.x + a3.y*xt.y + b3.x*xt.z + b3.y*xt.w;
    #pragma unroll
    for (int o = 4; o > 0; o >>= 1) {
        d0 += __shfl_xor_sync(gmask, d0, o);
        d1 += __shfl_xor_sync(gmask, d1, o);
        d2 += __shfl_xor_sync(gmask, d2, o);
        d3 += __shfl_xor_sync(gmask, d3, o);
    }
    const float w0 = v0 ? __expf(beta * d0) : 0.0f;
    const float w1 = v1 ? __expf(beta * d1) : 0.0f;
    const float w2 = v2 ? __expf(beta * d2) : 0.0f;
    const float w3 = v3 ? __expf(beta * d3) : 0.0f;
    const float c0 = w0 * r0, c1 = w1 * r1, c2 = w2 * r2, c3 = w3 * r3;
    acc.x = fmaf(c0, a0.x, fmaf(c1, a1.x, fmaf(c2, a2.x, fmaf(c3, a3.x, acc.x))));
    acc.y = fmaf(c0, a0.y, fmaf(c1, a1.y, fmaf(c2, a2.y, fmaf(c3, a3.y, acc.y))));
    acc.z = fmaf(c0, b0.x, fmaf(c1, b1.x, fmaf(c2, b2.x, fmaf(c3, b3.x, acc.z))));
    acc.w = fmaf(c0, b0.y, fmaf(c1, b1.y, fmaf(c2, b2.y, fmaf(c3, b3.y, acc.w))));
    den += (w0 + w1) + (w2 + w3);
}

__global__ void __launch_bounds__(256) k_agg(
    const float* __restrict__ W2,
    const float* __restrict__ b2,
    const float* __restrict__ beta_p,
    float* __restrict__ out)
{
    const int tid  = threadIdx.x;
    const int lane = tid & 31;
    const int g    = lane >> 3;
    const int sub  = lane & 7;
    const unsigned gmask = 0xFFu << (g * 8);
    const int n = blockIdx.x * 32 + (tid >> 5) * 4 + g;   // 100000 = 3125*32

    const float beta = *beta_p;
    const float4 xt = *(const float4*)&g_xnf[n * HID + sub * 4];
    const float nrm_n = g_nrm[n];
    int deg = g_cnt[n];
    if (deg > ELL_CAP) deg = ELL_CAP;
    const int* __restrict__ cols = &g_col[n * ELL_CAP];

    float d = xt.x*xt.x + xt.y*xt.y + xt.z*xt.z + xt.w*xt.w;
    #pragma unroll
    for (int o = 4; o > 0; o >>= 1) d += __shfl_xor_sync(gmask, d, o);
    float wl = __expf(beta * d);
    float cl = wl * nrm_n;
    float4 acc = make_float4(cl * xt.x, cl * xt.y, cl * xt.z, cl * xt.w);
    float  den = wl;

    for (int cb = 0; cb < deg; cb += 8) {
        const int cidx = cols[cb + sub];
        edge4(cb, 0, deg, cidx, gmask, n, sub, xt, beta, acc, den);
        edge4(cb, 4, deg, cidx, gmask, n, sub, xt, beta, acc, den);
    }

    const float inv = 1.0f / den;
    const float4 o4 = make_float4(acc.x * inv, acc.y * inv, acc.z * inv, acc.w * inv);

    const float4 w2a = *(const float4*)&W2[sub * 4];
    const float4 w2b = *(const float4*)&W2[HID + sub * 4];
    float p0 = o4.x * w2a.x + o4.y * w2a.y + o4.z * w2a.z + o4.w * w2a.w;
    float p1 = o4.x * w2b.x + o4.y * w2b.y + o4.z * w2b.z + o4.w * w2b.w;
    #pragma unroll
    for (int o = 4; o > 0; o >>= 1) {
        p0 += __shfl_xor_sync(gmask, p0, o);
        p1 += __shfl_xor_sync(gmask, p1, o);
    }

    if (sub == 0) {
        float l0 = p0 + b2[0];
        float l1 = p1 + b2[1];
        float m  = fmaxf(l0, l1);
        float z  = m + logf(expf(l0 - m) + expf(l1 - m));
        *(float2*)&out[n * 2] = make_float2(l0 - z, l1 - z);
    }
}

// ---------------------------------------------------------------------------
// Inputs (metadata order):
//   0: X [N,100] f32   1: lin1_w [32,100] f32   2: lin1_b [32] f32
//   3: beta scalar f32 4: lin2_w [2,32]  f32   5: lin2_b [2] f32
//   6: edge_index [2,E] i32 (row 0 = src, row 1 = tgt)
// Output: [N,2] f32 log-probs
// ---------------------------------------------------------------------------
extern "C" void kernel_launch(void* const* d_in, const int* in_sizes, int n_in,
                              void* d_out, int out_size)
{
    const float* X    = (const float*)d_in[0];
    const float* W1   = (const float*)d_in[1];
    const float* b1   = (const float*)d_in[2];
    const float* beta = (const float*)d_in[3];
    const float* W2   = (const float*)d_in[4];
    const float* b2   = (const float*)d_in[5];
    const int*   ei   = (const int*)  d_in[6];
    const int* esrc = ei;
    const int* etgt = ei + N_EDGES;
    float* out = (float*)d_out;

    const int smem_k1 = K1_NB * 25 * sizeof(float4);     // 51200 B
    cudaFuncSetAttribute(k1_lin, cudaFuncAttributeMaxDynamicSharedMemorySize,
                         smem_k1);

    const int g1 = (N_NODES + K1_NB - 1) / K1_NB;        // 782
    k1_lin<<<g1, K1_NB, smem_k1>>>(X, W1, b1);
    k_ell<<<(N_EDGES / 4 + 255) / 256, 256>>>(esrc, etgt);
    k_agg<<<N_NODES / 32, 256>>>(W2, b2, beta, out);
}

// round 12
// speedup vs baseline: 1.3522x; 1.3522x over previous
#include <cuda_runtime.h>
#include <cuda_fp16.h>
#include <cstdint>
#include <math.h>

#define N_NODES 100000
#define N_FEAT  100
#define HID     32
#define N_EDGES 1600000
#define NCHUNK  25          // N_FEAT/4 float4 chunks per W1 row
#define ELL_CAP 128         // max in-degree slot (Poisson(16): P(>128) ~ 0)
#define NB      16          // nodes per block in K1

// Scratch (static device globals — no allocations allowed)
__device__ float g_xnf[N_NODES * HID];                   // fp32 normalized feats
__device__ __align__(16) unsigned g_xnh[N_NODES * 16];   // half2-packed rows (64B)
__device__ float g_nrm[N_NODES];                         // row norms
__device__ int   g_cnt[N_NODES];                         // in-degree counters
__device__ int   g_col[N_NODES * ELL_CAP];               // ELL source lists

// ---------------- packed f32x2 helpers (sm_100+) ----------------
__device__ __forceinline__ unsigned long long ffma2(
    unsigned long long a, unsigned long long b, unsigned long long c) {
    unsigned long long d;
    asm("fma.rn.f32x2 %0, %1, %2, %3;" : "=l"(d) : "l"(a), "l"(b), "l"(c));
    return d;
}
__device__ __forceinline__ float unpack_add(unsigned long long v) {
    float lo, hi;
    asm("mov.b64 {%0, %1}, %2;" : "=f"(lo), "=f"(hi) : "l"(v));
    return lo + hi;
}

// ---------------------------------------------------------------------------
// K0: zero degree counters (runs on side stream, parallel with k1)
// ---------------------------------------------------------------------------
__global__ void k_zero() {
    int i = blockIdx.x * blockDim.x + threadIdx.x;
    if (i * 4 < N_NODES) *(int4*)&g_cnt[i * 4] = make_int4(0, 0, 0, 0);
}

// ---------------------------------------------------------------------------
// K1: x = relu(X @ W1^T + b1); xn = x/||x||; store xn (fp32 + half2) + nrm.
// 16 nodes/block, register-resident weights (f32x2), broadcast LDS.128.
// (R7-proven layout: 47.5us, occ 76%, issue 65%.)
// ---------------------------------------------------------------------------
__global__ void __launch_bounds__(256) k1_lin1_norm(
    const float* __restrict__ X,
    const float* __restrict__ W1,
    const float* __restrict__ b1)
{
    __shared__ float4 sX4[NB * NCHUNK];
    __shared__ float  psum[NB * 8 * 33];

    const int tid  = threadIdx.x;
    const int w    = tid >> 5;
    const int lane = tid & 31;

    const int base = (w < 7) ? 3 * w : 21;
    const int nch  = (w < 7) ? 3 : 4;

    const ulonglong2* W2v = (const ulonglong2*)W1;
    unsigned long long wlo[4], whi[4];
    #pragma unroll
    for (int j = 0; j < 4; j++) {
        if (j < nch) {
            ulonglong2 v = W2v[lane * NCHUNK + base + j];
            wlo[j] = v.x; whi[j] = v.y;
        } else { wlo[j] = 0ull; whi[j] = 0ull; }
    }

    const int node0 = blockIdx.x * NB;         // 100000 = 6250*16 exact
    const float4* X4 = (const float4*)X;
    for (int i = tid; i < NB * NCHUNK; i += 256) {
        int n = i / NCHUNK, c = i % NCHUNK;
        sX4[i] = X4[(size_t)(node0 + n) * NCHUNK + c];
    }
    __syncthreads();

    const ulonglong2* sX2v = (const ulonglong2*)sX4;
    #pragma unroll
    for (int n = 0; n < NB; n++) {
        unsigned long long a0 = 0ull, a1 = 0ull;
        #pragma unroll
        for (int j = 0; j < 4; j++) {
            if (j < nch) {
                ulonglong2 x = sX2v[n * NCHUNK + base + j];  // broadcast LDS.128
                a0 = ffma2(x.x, wlo[j], a0);
                a1 = ffma2(x.y, whi[j], a1);
            }
        }
        psum[(n * 8 + w) * 33 + lane] = unpack_add(a0) + unpack_add(a1);
    }
    __syncthreads();

    // warp w finalizes nodes w and w+8 (lane = hid)
    #pragma unroll
    for (int rep = 0; rep < 2; rep++) {
        const int n = w + rep * 8;
        float v = b1[lane];
        #pragma unroll
        for (int ww = 0; ww < 8; ww++)
            v += psum[(n * 8 + ww) * 33 + lane];
        v = fmaxf(v, 0.0f);

        float s = v * v;
        #pragma unroll
        for (int o = 16; o > 0; o >>= 1) s += __shfl_xor_sync(0xffffffffu, s, o);
        float nrm = fmaxf(sqrtf(s), 1e-12f);

        const int node = node0 + n;
        const float xnv = v / nrm;
        g_xnf[node * HID + lane] = xnv;

        // pack half2 pairs: even lane stores (lane, lane+1)
        float hi = __shfl_down_sync(0xffffffffu, xnv, 1);
        if ((lane & 1) == 0) {
            __half2 p = __floats2half2_rn(xnv, hi);
            g_xnh[node * 16 + (lane >> 1)] = *(unsigned*)&p;
        }
        if (lane == 0) g_nrm[node] = nrm;
    }
}

// ---------------------------------------------------------------------------
// ELL build: 4 edges per thread, int4 reads, 4 independent atomic chains.
// ---------------------------------------------------------------------------
__global__ void k_ell(const int* __restrict__ esrc,
                      const int* __restrict__ etgt) {
    int e0 = (blockIdx.x * blockDim.x + threadIdx.x) * 4;
    if (e0 >= N_EDGES) return;
    int4 s = *(const int4*)&esrc[e0];
    int4 t = *(const int4*)&etgt[e0];
    int p0 = atomicAdd(&g_cnt[t.x], 1);
    int p1 = atomicAdd(&g_cnt[t.y], 1);
    int p2 = atomicAdd(&g_cnt[t.z], 1);
    int p3 = atomicAdd(&g_cnt[t.w], 1);
    if (p0 < ELL_CAP) g_col[t.x * ELL_CAP + p0] = s.x;
    if (p1 < ELL_CAP) g_col[t.y * ELL_CAP + p1] = s.y;
    if (p2 < ELL_CAP) g_col[t.z * ELL_CAP + p2] = s.z;
    if (p3 < ELL_CAP) g_col[t.w * ELL_CAP + p3] = s.w;
}

// ---------------------------------------------------------------------------
// K_AGG: 8-lane group owns one node (4 nodes/warp); fp16 gathers; 4-way MLP.
// ---------------------------------------------------------------------------
__device__ __forceinline__ void edge4(
    int cb, int jj, int deg, int cidx, unsigned gmask, int n, int sub,
    const float4 xt, float beta, float4& acc, float& den)
{
    const bool v0 = (cb + jj     < deg);
    const bool v1 = (cb + jj + 1 < deg);
    const bool v2 = (cb + jj + 2 < deg);
    const bool v3 = (cb + jj + 3 < deg);
    int s0 = __shfl_sync(gmask, cidx, jj,     8);
    int s1 = __shfl_sync(gmask, cidx, jj + 1, 8);
    int s2 = __shfl_sync(gmask, cidx, jj + 2, 8);
    int s3 = __shfl_sync(gmask, cidx, jj + 3, 8);
    s0 = v0 ? s0 : n;  s1 = v1 ? s1 : n;
    s2 = v2 ? s2 : n;  s3 = v3 ? s3 : n;

    const uint2 u0 = *(const uint2*)&g_xnh[s0 * 16 + sub * 2];
    const uint2 u1 = *(const uint2*)&g_xnh[s1 * 16 + sub * 2];
    const uint2 u2 = *(const uint2*)&g_xnh[s2 * 16 + sub * 2];
    const uint2 u3 = *(const uint2*)&g_xnh[s3 * 16 + sub * 2];
    const float r0 = g_nrm[s0], r1 = g_nrm[s1];
    const float r2 = g_nrm[s2], r3 = g_nrm[s3];

    float2 a0 = __half22float2(*(const __half2*)&u0.x);
    float2 b0 = __half22float2(*(const __half2*)&u0.y);
    float2 a1 = __half22float2(*(const __half2*)&u1.x);
    float2 b1 = __half22float2(*(const __half2*)&u1.y);
    float2 a2 = __half22float2(*(const __half2*)&u2.x);
    float2 b2 = __half22float2(*(const __half2*)&u2.y);
    float2 a3 = __half22float2(*(const __half2*)&u3.x);
    float2 b3 = __half22float2(*(const __half2*)&u3.y);

    float d0 = a0.x*xt.x + a0.y*xt.y + b0.x*xt.z + b0.y*xt.w;
    float d1 = a1.x*xt.x + a1.y*xt.y + b1.x*xt.z + b1.y*xt.w;
    float d2 = a2.x*xt.x + a2.y*xt.y + b2.x*xt.z + b2.y*xt.w;
    float d3 = a3.x*xt.x + a3.y*xt.y + b3.x*xt.z + b3.y*xt.w;
    #pragma unroll
    for (int o = 4; o > 0; o >>= 1) {
        d0 += __shfl_xor_sync(gmask, d0, o);
        d1 += __shfl_xor_sync(gmask, d1, o);
        d2 += __shfl_xor_sync(gmask, d2, o);
        d3 += __shfl_xor_sync(gmask, d3, o);
    }
    const float w0 = v0 ? __expf(beta * d0) : 0.0f;
    const float w1 = v1 ? __expf(beta * d1) : 0.0f;
    const float w2 = v2 ? __expf(beta * d2) : 0.0f;
    const float w3 = v3 ? __expf(beta * d3) : 0.0f;
    const float c0 = w0 * r0, c1 = w1 * r1, c2 = w2 * r2, c3 = w3 * r3;
    acc.x = fmaf(c0, a0.x, fmaf(c1, a1.x, fmaf(c2, a2.x, fmaf(c3, a3.x, acc.x))));
    acc.y = fmaf(c0, a0.y, fmaf(c1, a1.y, fmaf(c2, a2.y, fmaf(c3, a3.y, acc.y))));
    acc.z = fmaf(c0, b0.x, fmaf(c1, b1.x, fmaf(c2, b2.x, fmaf(c3, b3.x, acc.z))));
    acc.w = fmaf(c0, b0.y, fmaf(c1, b1.y, fmaf(c2, b2.y, fmaf(c3, b3.y, acc.w))));
    den += (w0 + w1) + (w2 + w3);
}

__global__ void __launch_bounds__(256) k_agg(
    const float* __restrict__ W2,
    const float* __restrict__ b2,
    const float* __restrict__ beta_p,
    float* __restrict__ out)
{
    const int tid  = threadIdx.x;
    const int lane = tid & 31;
    const int g    = lane >> 3;
    const int sub  = lane & 7;
    const unsigned gmask = 0xFFu << (g * 8);
    const int n = blockIdx.x * 32 + (tid >> 5) * 4 + g;   // 100000 = 3125*32

    const float beta = *beta_p;
    const float4 xt = *(const float4*)&g_xnf[n * HID + sub * 4];
    const float nrm_n = g_nrm[n];
    int deg = g_cnt[n];
    if (deg > ELL_CAP) deg = ELL_CAP;
    const int* __restrict__ cols = &g_col[n * ELL_CAP];

    float d = xt.x*xt.x + xt.y*xt.y + xt.z*xt.z + xt.w*xt.w;
    #pragma unroll
    for (int o = 4; o > 0; o >>= 1) d += __shfl_xor_sync(gmask, d, o);
    float wl = __expf(beta * d);
    float cl = wl * nrm_n;
    float4 acc = make_float4(cl * xt.x, cl * xt.y, cl * xt.z, cl * xt.w);
    float  den = wl;

    for (int cb = 0; cb < deg; cb += 8) {
        const int cidx = cols[cb + sub];
        edge4(cb, 0, deg, cidx, gmask, n, sub, xt, beta, acc, den);
        edge4(cb, 4, deg, cidx, gmask, n, sub, xt, beta, acc, den);
    }

    const float inv = 1.0f / den;
    const float4 o4 = make_float4(acc.x * inv, acc.y * inv, acc.z * inv, acc.w * inv);

    const float4 w2a = *(const float4*)&W2[sub * 4];
    const float4 w2b = *(const float4*)&W2[HID + sub * 4];
    float p0 = o4.x * w2a.x + o4.y * w2a.y + o4.z * w2a.z + o4.w * w2a.w;
    float p1 = o4.x * w2b.x + o4.y * w2b.y + o4.z * w2b.z + o4.w * w2b.w;
    #pragma unroll
    for (int o = 4; o > 0; o >>= 1) {
        p0 += __shfl_xor_sync(gmask, p0, o);
        p1 += __shfl_xor_sync(gmask, p1, o);
    }

    if (sub == 0) {
        float l0 = p0 + b2[0];
        float l1 = p1 + b2[1];
        float m  = fmaxf(l0, l1);
        float z  = m + logf(expf(l0 - m) + expf(l1 - m));
        *(float2*)&out[n * 2] = make_float2(l0 - z, l1 - z);
    }
}

// ---------------------------------------------------------------------------
// Launch with stream overlap: {k_zero -> k_ell} on side stream runs
// concurrently with k1 on the main stream; fork/join via events so the
// dependency DAG is captured correctly into the graph.
// Inputs (metadata order):
//   0: X [N,100] f32   1: lin1_w [32,100] f32   2: lin1_b [32] f32
//   3: beta scalar f32 4: lin2_w [2,32]  f32   5: lin2_b [2] f32
//   6: edge_index [2,E] i32 (row 0 = src, row 1 = tgt)
// Output: [N,2] f32 log-probs
// ---------------------------------------------------------------------------
extern "C" void kernel_launch(void* const* d_in, const int* in_sizes, int n_in,
                              void* d_out, int out_size)
{
    const float* X    = (const float*)d_in[0];
    const float* W1   = (const float*)d_in[1];
    const float* b1   = (const float*)d_in[2];
    const float* beta = (const float*)d_in[3];
    const float* W2   = (const float*)d_in[4];
    const float* b2   = (const float*)d_in[5];
    const int*   ei   = (const int*)  d_in[6];
    const int* esrc = ei;
    const int* etgt = ei + N_EDGES;
    float* out = (float*)d_out;

    cudaStream_t s2;
    cudaStreamCreateWithFlags(&s2, cudaStreamNonBlocking);
    cudaEvent_t eFork, eJoin;
    cudaEventCreateWithFlags(&eFork, cudaEventDisableTiming);
    cudaEventCreateWithFlags(&eJoin, cudaEventDisableTiming);

    // fork: side stream joins the (possibly capturing) main stream
    cudaEventRecord(eFork, 0);
    cudaStreamWaitEvent(s2, eFork, 0);

    // edge pipeline on s2 (independent of k1)
    k_zero<<<(N_NODES / 4 + 255) / 256, 256, 0, s2>>>();
    k_ell<<<(N_EDGES / 4 + 255) / 256, 256, 0, s2>>>(esrc, etgt);

    // node pipeline on main stream
    k1_lin1_norm<<<N_NODES / NB, 256>>>(X, W1, b1);

    // join: main stream waits for edge pipeline
    cudaEventRecord(eJoin, s2);
    cudaStreamWaitEvent(0, eJoin, 0);

    k_agg<<<N_NODES / 32, 256>>>(W2, b2, beta, out);

    cudaEventDestroy(eFork);
    cudaEventDestroy(eJoin);
    cudaStreamDestroy(s2);
}